// round 1
// baseline (speedup 1.0000x reference)
#include <cuda_runtime.h>
#include <cuda_bf16.h>

// Problem dims (fixed by the dataset; runtime values derived from in_sizes)
#define NMAX 100000
#define HDIM 64

// ---------------- scratch (device globals: no allocation allowed) ----------
__device__ __align__(256) float g_deg[NMAX];          // degree, then 1/max(deg,1)
__device__ __align__(256) float g_sum[NMAX * HDIM];   // scatter accumulator
__device__ __align__(256) float g_pre[NMAX * HDIM];   // pre-BN activations
__device__ __align__(256) float g_h1[NMAX * HDIM];    // layer-1 output
__device__ __align__(256) float g_colsum[HDIM];
__device__ __align__(256) float g_colsq[HDIM];
__device__ __align__(256) float g_scale[HDIM];
__device__ __align__(256) float g_shift[HDIM];
__device__ int g_is64;

// ---------------- edge-index dtype detection --------------------------------
// jnp.int64 without jax x64 silently becomes int32. Values are in [0, 1e5),
// so under an int64 layout every odd 32-bit word is zero. Under int32, odd
// words are random node ids (P(all 4096 zero) ~ 0).
__global__ void detect_kernel(const unsigned int* __restrict__ ei32) {
    __shared__ unsigned int acc;
    if (threadIdx.x == 0) acc = 0u;
    __syncthreads();
    unsigned int v = 0u;
    for (int i = threadIdx.x; i < 4096; i += blockDim.x) v |= ei32[2 * i + 1];
    atomicOr(&acc, v);
    __syncthreads();
    if (threadIdx.x == 0) g_is64 = (acc == 0u) ? 1 : 0;
}

__device__ __forceinline__ long long load_idx(const void* ei, long long pos, int is64) {
    if (is64) return ((const long long*)ei)[pos];
    return (long long)((const int*)ei)[pos];
}

// ---------------- zeroing (g_sum + BN stats [+ deg]) ------------------------
__global__ void prep_kernel(long long nvec, int n, int zero_deg) {
    long long i = (long long)blockIdx.x * blockDim.x + threadIdx.x;
    if (i < nvec) reinterpret_cast<float4*>(g_sum)[i] = make_float4(0.f, 0.f, 0.f, 0.f);
    if (i < 16) {
        reinterpret_cast<float4*>(g_colsum)[i] = make_float4(0.f, 0.f, 0.f, 0.f);
        reinterpret_cast<float4*>(g_colsq)[i]  = make_float4(0.f, 0.f, 0.f, 0.f);
    }
    if (zero_deg && i < n) g_deg[i] = 0.f;
}

// ---------------- degree -----------------------------------------------------
__global__ void deg_kernel(const void* __restrict__ ei, long long E) {
    long long e = (long long)blockIdx.x * blockDim.x + threadIdx.x;
    if (e >= E) return;
    int is64 = g_is64;
    int d = (int)load_idx(ei, E + e, is64);
    atomicAdd(&g_deg[d], 1.0f);
}

__global__ void inv_kernel(int n) {
    int i = blockIdx.x * blockDim.x + threadIdx.x;
    if (i < n) g_deg[i] = 1.0f / fmaxf(g_deg[i], 1.0f);
}

// ---------------- edge gather + scatter-add (vectorized RED) ----------------
// thread t handles edge e = t/16, float4 chunk c = t%16.
__global__ void __launch_bounds__(256) scatter_kernel(const float* __restrict__ feat,
                                                      const void* __restrict__ ei,
                                                      long long E) {
    long long idx = (long long)blockIdx.x * blockDim.x + threadIdx.x;
    long long e = idx >> 4;
    int c = (int)(idx & 15);
    if (e >= E) return;
    int is64 = g_is64;
    long long s = load_idx(ei, e, is64);
    long long d = load_idx(ei, E + e, is64);
    float4 v = __ldg((const float4*)(feat + s * HDIM + c * 4));
    float* p = g_sum + d * HDIM + c * 4;
    asm volatile("red.global.add.v4.f32 [%0], {%1,%2,%3,%4};"
                 :: "l"(p), "f"(v.x), "f"(v.y), "f"(v.z), "f"(v.w)
                 : "memory");
}

// ---------------- per-node linear: out = inv*(sum@Wl^T) + bl + x@Wr^T -------
// Warp per node; lane owns output columns (2*lane, 2*lane+1). Weights stored
// transposed in SMEM -> conflict-free float2 reads. BN sum/sumsq accumulated
// in registers (fixed columns per lane), flushed once via global atomics.
__global__ void __launch_bounds__(256) linear_kernel(const float* __restrict__ xin,
                                                     const float* __restrict__ Wl,
                                                     const float* __restrict__ bl,
                                                     const float* __restrict__ Wr,
                                                     int n) {
    __shared__ float WlT[HDIM * HDIM];
    __shared__ float WrT[HDIM * HDIM];
    __shared__ float shS[8][HDIM];
    __shared__ float shX[8][HDIM];
    int tid = threadIdx.x;
    for (int i = tid; i < HDIM * HDIM; i += 256) {
        int j = i >> 6, k = i & 63;
        WlT[k * HDIM + j] = Wl[i];
        WrT[k * HDIM + j] = Wr[i];
    }
    __syncthreads();
    int warp = tid >> 5, lane = tid & 31;
    int j0 = lane * 2;
    float b0 = bl[j0], b1 = bl[j0 + 1];
    float s0 = 0.f, s1 = 0.f, q0 = 0.f, q1 = 0.f;

    for (long long node = (long long)blockIdx.x * 8 + warp; node < n;
         node += (long long)gridDim.x * 8) {
        float2 a = ((const float2*)(g_sum + node * HDIM))[lane];
        float2 b = ((const float2*)(xin + node * HDIM))[lane];
        shS[warp][j0] = a.x; shS[warp][j0 + 1] = a.y;
        shX[warp][j0] = b.x; shX[warp][j0 + 1] = b.y;
        __syncwarp();
        float aL0 = 0.f, aL1 = 0.f, aR0 = 0.f, aR1 = 0.f;
#pragma unroll
        for (int k = 0; k < HDIM; k++) {
            float av = shS[warp][k];
            float xv = shX[warp][k];
            float2 wl = ((const float2*)(WlT + k * HDIM))[lane];
            float2 wr = ((const float2*)(WrT + k * HDIM))[lane];
            aL0 = fmaf(av, wl.x, aL0); aL1 = fmaf(av, wl.y, aL1);
            aR0 = fmaf(xv, wr.x, aR0); aR1 = fmaf(xv, wr.y, aR1);
        }
        float inv = g_deg[node];
        float o0 = fmaf(aL0, inv, b0) + aR0;
        float o1 = fmaf(aL1, inv, b1) + aR1;
        ((float2*)(g_pre + node * HDIM))[lane] = make_float2(o0, o1);
        s0 += o0; s1 += o1; q0 += o0 * o0; q1 += o1 * o1;
        __syncwarp();
    }
    atomicAdd(&g_colsum[j0], s0);
    atomicAdd(&g_colsum[j0 + 1], s1);
    atomicAdd(&g_colsq[j0], q0);
    atomicAdd(&g_colsq[j0 + 1], q1);
}

// ---------------- BN stats -> scale/shift ------------------------------------
__global__ void bn_kernel(const float* __restrict__ gamma, const float* __restrict__ beta,
                          float fn) {
    int j = threadIdx.x;
    float mean = g_colsum[j] / fn;
    float var = g_colsq[j] / fn - mean * mean;
    float sc = gamma[j] * rsqrtf(var + 1e-5f);
    g_scale[j] = sc;
    g_shift[j] = beta[j] - mean * sc;
}

// ---------------- normalize + relu (layer 1) ---------------------------------
__global__ void __launch_bounds__(256) norm_kernel(long long nvec) {
    long long i = (long long)blockIdx.x * blockDim.x + threadIdx.x;
    if (i >= nvec) return;
    int col = (int)(i & 15) * 4;
    float4 v = ((const float4*)g_pre)[i];
    float4 sc = *(const float4*)(g_scale + col);
    float4 sh = *(const float4*)(g_shift + col);
    v.x = fmaxf(fmaf(v.x, sc.x, sh.x), 0.f);
    v.y = fmaxf(fmaf(v.y, sc.y, sh.y), 0.f);
    v.z = fmaxf(fmaf(v.z, sc.z, sh.z), 0.f);
    v.w = fmaxf(fmaf(v.w, sc.w, sh.w), 0.f);
    ((float4*)g_h1)[i] = v;
}

// ---------------- layer-2 normalize + relu + decoder (fused) -----------------
// Writes h to d_out[N*C ..] and logits to d_out[0 .. N*C).
__global__ void __launch_bounds__(256) final_kernel(const float* __restrict__ Wd,
                                                    const float* __restrict__ bd,
                                                    float* __restrict__ out,
                                                    int n, int C) {
    __shared__ float WdT[HDIM * 48];   // padded stride 48, zero-filled
    __shared__ float shh[8][HDIM];
    __shared__ float sbd[48];
    int tid = threadIdx.x;
    for (int i = tid; i < HDIM * 48; i += 256) WdT[i] = 0.f;
    if (tid < 48) sbd[tid] = (tid < C) ? bd[tid] : 0.f;
    __syncthreads();
    for (int i = tid; i < C * HDIM; i += 256) {
        int c = i >> 6, k = i & 63;
        WdT[k * 48 + c] = Wd[i];
    }
    __syncthreads();

    int warp = tid >> 5, lane = tid & 31;
    int j0 = 2 * lane;
    float sc0 = g_scale[j0], sc1 = g_scale[j0 + 1];
    float sh0 = g_shift[j0], sh1 = g_shift[j0 + 1];
    float* hout = out + (long long)n * C;

    for (long long node = (long long)blockIdx.x * 8 + warp; node < n;
         node += (long long)gridDim.x * 8) {
        float2 p = ((const float2*)(g_pre + node * HDIM))[lane];
        float h0 = fmaxf(fmaf(p.x, sc0, sh0), 0.f);
        float h1 = fmaxf(fmaf(p.y, sc1, sh1), 0.f);
        ((float2*)(hout + node * HDIM))[lane] = make_float2(h0, h1);
        shh[warp][j0] = h0; shh[warp][j0 + 1] = h1;
        __syncwarp();
        float a0 = 0.f, a1 = 0.f;
#pragma unroll
        for (int k = 0; k < HDIM; k++) {
            float hv = shh[warp][k];
            a0 = fmaf(hv, WdT[k * 48 + lane], a0);
            a1 = fmaf(hv, WdT[k * 48 + lane + 32], a1);
        }
        out[node * C + lane] = a0 + sbd[lane];
        if (lane + 32 < C) out[node * C + lane + 32] = a1 + sbd[lane + 32];
        __syncwarp();
    }
}

// ---------------- launch -----------------------------------------------------
extern "C" void kernel_launch(void* const* d_in, const int* in_sizes, int n_in,
                              void* d_out, int out_size) {
    const float* x   = (const float*)d_in[0];
    const void*  ei  = d_in[1];
    const float* W1l = (const float*)d_in[2];
    const float* b1l = (const float*)d_in[3];
    const float* W1r = (const float*)d_in[4];
    const float* g1  = (const float*)d_in[5];
    const float* be1 = (const float*)d_in[6];
    const float* W2l = (const float*)d_in[7];
    const float* b2l = (const float*)d_in[8];
    const float* W2r = (const float*)d_in[9];
    const float* g2  = (const float*)d_in[10];
    const float* be2 = (const float*)d_in[11];
    const float* Wd  = (const float*)d_in[12];
    const float* bd  = (const float*)d_in[13];
    float* out = (float*)d_out;

    int n = in_sizes[0] / HDIM;              // 100000
    long long E = (long long)in_sizes[1] / 2; // 1600000
    int C = in_sizes[12] / HDIM;             // 40

    float* p_h1 = nullptr;
    cudaGetSymbolAddress((void**)&p_h1, g_h1);

    long long nvec = (long long)n * 16;                 // float4 chunks of n*64
    int zb = (int)((nvec + 255) / 256);
    int eb = (int)((E + 255) / 256);
    long long sthreads = E * 16;
    int sb = (int)((sthreads + 255) / 256);
    int LIN_GRID = 592;

    detect_kernel<<<1, 256>>>((const unsigned int*)ei);

    // ---- layer 1 ----
    prep_kernel<<<zb, 256>>>(nvec, n, 1);
    deg_kernel<<<eb, 256>>>(ei, E);
    inv_kernel<<<(n + 255) / 256, 256>>>(n);
    scatter_kernel<<<sb, 256>>>(x, ei, E);
    linear_kernel<<<LIN_GRID, 256>>>(x, W1l, b1l, W1r, n);
    bn_kernel<<<1, HDIM>>>(g1, be1, (float)n);
    norm_kernel<<<zb, 256>>>(nvec);

    // ---- layer 2 ----
    prep_kernel<<<zb, 256>>>(nvec, n, 0);
    scatter_kernel<<<sb, 256>>>(p_h1, ei, E);
    linear_kernel<<<LIN_GRID, 256>>>(p_h1, W2l, b2l, W2r, n);
    bn_kernel<<<1, HDIM>>>(g2, be2, (float)n);

    // ---- normalize + decoder (fused) ----
    final_kernel<<<LIN_GRID, 256>>>(Wd, bd, out, n, C);
}

// round 2
// speedup vs baseline: 1.3397x; 1.3397x over previous
#include <cuda_runtime.h>
#include <cuda_bf16.h>

#define NMAX 100000
#define EMAX 1600000
#define HDIM 64

typedef unsigned long long ull;

// ---------------- scratch (device globals; no allocation allowed) -----------
__device__ __align__(256) float g_deg[NMAX];          // 1/max(deg,1)
__device__ __align__(256) int   g_degi[NMAX];         // int degree
__device__ __align__(256) int   g_off[NMAX + 1];      // CSR row offsets (by dst)
__device__ __align__(256) int   g_cur[NMAX];          // fill cursors
__device__ __align__(256) int   g_csr[EMAX];          // src ids grouped by dst
__device__ __align__(256) float g_pre[NMAX * HDIM];   // pre-BN activations
__device__ __align__(256) float g_h1[NMAX * HDIM];    // layer-1 output
__device__ float g_colsum[HDIM];
__device__ float g_colsq[HDIM];
__device__ float g_scale[HDIM];
__device__ float g_shift[HDIM];
__device__ int   g_part[512];
__device__ int   g_is64;

// packed fp32x2 FMA (Blackwell): acc = a*b + acc, two MACs per instruction
#define FMA2(acc, a, b) \
    asm("fma.rn.f32x2 %0, %1, %2, %0;" : "+l"(acc) : "l"(a), "l"(b))

__device__ __forceinline__ float2 unpack2(ull v) {
    float2 r;
    asm("mov.b64 {%0, %1}, %2;" : "=f"(r.x), "=f"(r.y) : "l"(v));
    return r;
}

// ---------------- edge-index dtype detection --------------------------------
// jnp.int64 without jax x64 silently becomes int32. Node ids < 1e5, so under
// an int64 layout every odd 32-bit word is zero.
__global__ void detect_kernel(const unsigned int* __restrict__ ei32) {
    __shared__ unsigned int acc;
    if (threadIdx.x == 0) acc = 0u;
    __syncthreads();
    unsigned int v = 0u;
    for (int i = threadIdx.x; i < 4096; i += blockDim.x) v |= ei32[2 * i + 1];
    atomicOr(&acc, v);
    __syncthreads();
    if (threadIdx.x == 0) g_is64 = (acc == 0u) ? 1 : 0;
}

__device__ __forceinline__ long long load_idx(const void* ei, long long pos, int is64) {
    if (is64) return ((const long long*)ei)[pos];
    return (long long)((const int*)ei)[pos];
}

// ---------------- CSR build --------------------------------------------------
__global__ void zero_kernel(int n) {
    int i = blockIdx.x * blockDim.x + threadIdx.x;
    if (i < n) g_degi[i] = 0;
    if (i < HDIM) { g_colsum[i] = 0.f; g_colsq[i] = 0.f; }
}

__global__ void zero_stats() {
    int i = threadIdx.x;
    g_colsum[i] = 0.f; g_colsq[i] = 0.f;
}

__global__ void hist_kernel(const void* __restrict__ ei, long long E) {
    long long e = (long long)blockIdx.x * blockDim.x + threadIdx.x;
    if (e >= E) return;
    int d = (int)load_idx(ei, E + e, g_is64);
    atomicAdd(&g_degi[d], 1);
}

__global__ void scan_part(int n) {
    __shared__ int s[512];
    int t = threadIdx.x;
    int i = blockIdx.x * 512 + t;
    s[t] = (i < n) ? g_degi[i] : 0;
    __syncthreads();
    for (int d = 256; d > 0; d >>= 1) {
        if (t < d) s[t] += s[t + d];
        __syncthreads();
    }
    if (t == 0) g_part[blockIdx.x] = s[0];
}

__global__ void scan_top(int nb) {
    __shared__ int s[512];
    int t = threadIdx.x;
    int v = (t < nb) ? g_part[t] : 0;
    s[t] = v;
    __syncthreads();
    for (int d = 1; d < 512; d <<= 1) {
        int add = (t >= d) ? s[t - d] : 0;
        __syncthreads();
        s[t] += add;
        __syncthreads();
    }
    if (t < nb) g_part[t] = s[t] - v;   // exclusive
}

__global__ void scan_final(int n) {
    __shared__ int s[512];
    int t = threadIdx.x;
    int i = blockIdx.x * 512 + t;
    int v = (i < n) ? g_degi[i] : 0;
    s[t] = v;
    __syncthreads();
    for (int d = 1; d < 512; d <<= 1) {
        int add = (t >= d) ? s[t - d] : 0;
        __syncthreads();
        s[t] += add;
        __syncthreads();
    }
    int excl = s[t] - v + g_part[blockIdx.x];
    if (i < n) {
        g_off[i] = excl;
        g_cur[i] = excl;
        g_deg[i] = 1.0f / fmaxf((float)v, 1.0f);
        if (i == n - 1) g_off[n] = excl + v;
    }
}

__global__ void fill_kernel(const void* __restrict__ ei, long long E) {
    long long e = (long long)blockIdx.x * blockDim.x + threadIdx.x;
    if (e >= E) return;
    int is64 = g_is64;
    int s = (int)load_idx(ei, e, is64);
    int d = (int)load_idx(ei, E + e, is64);
    int pos = atomicAdd(&g_cur[d], 1);
    g_csr[pos] = s;
}

// ---------------- fused layer: CSR gather-mean + Wl/Wr GEMV + BN stats ------
// 128 threads (4 warps); each warp processes 4 nodes per iteration.
// Weights in smem re-laid out as sW[m][kpair][lane] = {W[row][2kp], W[row][2kp+1]}
// where row = 2*lane + (m&1), m<2 -> Wl, m>=2 -> Wr. Conflict-free LDS.64.
// GEMV uses fma.rn.f32x2 over even/odd-k pairs; horizontal add at the end.
__global__ void __launch_bounds__(128, 4) layer_kernel(
    const float* __restrict__ xin,
    const float* __restrict__ Wl, const float* __restrict__ bl,
    const float* __restrict__ Wr, int n)
{
    __shared__ __align__(16) ull   sW[4][32][32];       // 32 KB
    __shared__ __align__(16) float shS[4][4][HDIM];     // 4 KB
    __shared__ __align__(16) float shX[4][4][HDIM];     // 4 KB
    __shared__ int shNb[4][32];

    int tid = threadIdx.x;
    for (int i = tid; i < 4096; i += 128) {
        int m = i >> 10, kp = (i >> 5) & 31, ln = i & 31;
        int row = 2 * ln + (m & 1);
        const float* Ws = (m < 2) ? Wl : Wr;
        sW[m][kp][ln] = ((const ull*)Ws)[row * 32 + kp];
    }
    __syncthreads();

    int warp = tid >> 5, lane = tid & 31;
    int j0 = 2 * lane;
    float b0 = bl[j0], b1 = bl[j0 + 1];
    float s0 = 0.f, s1 = 0.f, q0 = 0.f, q1 = 0.f;

    for (long long blk = (long long)blockIdx.x * 4 + warp; blk * 4 < n;
         blk += (long long)gridDim.x * 4) {
        long long node0 = blk * 4;
        int nvalid = (n - node0 >= 4) ? 4 : (int)(n - node0);

        // ---- gather mean-aggregated neighbors + root features into smem ----
        for (int nd = 0; nd < 4; nd++) {
            float ax = 0.f, ay = 0.f;
            if (nd < nvalid) {
                long long node = node0 + nd;
                int st = g_off[node], en = g_off[node + 1];
                for (int b = st; b < en; b += 32) {
                    int cnt = min(32, en - b);
                    if (lane < cnt) shNb[warp][lane] = g_csr[b + lane];
                    __syncwarp();
                    int j = 0;
                    for (; j + 4 <= cnt; j += 4) {
                        long long a0 = (long long)shNb[warp][j]     * HDIM;
                        long long a1 = (long long)shNb[warp][j + 1] * HDIM;
                        long long a2 = (long long)shNb[warp][j + 2] * HDIM;
                        long long a3 = (long long)shNb[warp][j + 3] * HDIM;
                        float2 v0 = __ldg((const float2*)(xin + a0) + lane);
                        float2 v1 = __ldg((const float2*)(xin + a1) + lane);
                        float2 v2 = __ldg((const float2*)(xin + a2) + lane);
                        float2 v3 = __ldg((const float2*)(xin + a3) + lane);
                        ax += (v0.x + v1.x) + (v2.x + v3.x);
                        ay += (v0.y + v1.y) + (v2.y + v3.y);
                    }
                    for (; j < cnt; j++) {
                        float2 v = __ldg((const float2*)(xin +
                                     (long long)shNb[warp][j] * HDIM) + lane);
                        ax += v.x; ay += v.y;
                    }
                    __syncwarp();
                }
                float inv = g_deg[node];
                ax *= inv; ay *= inv;
                float2 xv = __ldg((const float2*)(xin + node * HDIM) + lane);
                shX[warp][nd][j0] = xv.x; shX[warp][nd][j0 + 1] = xv.y;
            } else {
                shX[warp][nd][j0] = 0.f; shX[warp][nd][j0 + 1] = 0.f;
            }
            shS[warp][nd][j0] = ax; shS[warp][nd][j0 + 1] = ay;
        }
        __syncwarp();

        // ---- GEMV: 4 nodes x (mean@Wl^T, x@Wr^T), packed f32x2 ----
        ull aL0[4] = {0,0,0,0}, aL1[4] = {0,0,0,0};
        ull aR0[4] = {0,0,0,0}, aR1[4] = {0,0,0,0};
#pragma unroll 8
        for (int kp = 0; kp < 32; kp++) {
            ull wl0 = sW[0][kp][lane];
            ull wl1 = sW[1][kp][lane];
            ull wr0 = sW[2][kp][lane];
            ull wr1 = sW[3][kp][lane];
#pragma unroll
            for (int nd = 0; nd < 4; nd++) {
                ull v  = *(const ull*)&shS[warp][nd][kp * 2];
                ull xv = *(const ull*)&shX[warp][nd][kp * 2];
                FMA2(aL0[nd], v,  wl0);
                FMA2(aL1[nd], v,  wl1);
                FMA2(aR0[nd], xv, wr0);
                FMA2(aR1[nd], xv, wr1);
            }
        }
#pragma unroll
        for (int nd = 0; nd < 4; nd++) {
            if (nd < nvalid) {
                float2 l0 = unpack2(aL0[nd]), l1 = unpack2(aL1[nd]);
                float2 r0 = unpack2(aR0[nd]), r1 = unpack2(aR1[nd]);
                float o0 = (l0.x + l0.y) + (r0.x + r0.y) + b0;
                float o1 = (l1.x + l1.y) + (r1.x + r1.y) + b1;
                long long node = node0 + nd;
                ((float2*)(g_pre + node * HDIM))[lane] = make_float2(o0, o1);
                s0 += o0; s1 += o1; q0 += o0 * o0; q1 += o1 * o1;
            }
        }
        __syncwarp();
    }
    atomicAdd(&g_colsum[j0],     s0);
    atomicAdd(&g_colsum[j0 + 1], s1);
    atomicAdd(&g_colsq[j0],      q0);
    atomicAdd(&g_colsq[j0 + 1],  q1);
}

// ---------------- BN stats -> scale/shift ------------------------------------
__global__ void bn_kernel(const float* __restrict__ gamma,
                          const float* __restrict__ beta, float fn) {
    int j = threadIdx.x;
    float mean = g_colsum[j] / fn;
    float var = g_colsq[j] / fn - mean * mean;
    float sc = gamma[j] * rsqrtf(var + 1e-5f);
    g_scale[j] = sc;
    g_shift[j] = beta[j] - mean * sc;
}

// ---------------- normalize + relu (layer 1) ---------------------------------
__global__ void __launch_bounds__(256) norm_kernel(long long nvec) {
    long long i = (long long)blockIdx.x * blockDim.x + threadIdx.x;
    if (i >= nvec) return;
    int col = (int)(i & 15) * 4;
    float4 v = ((const float4*)g_pre)[i];
    float4 sc = *(const float4*)(g_scale + col);
    float4 sh = *(const float4*)(g_shift + col);
    v.x = fmaxf(fmaf(v.x, sc.x, sh.x), 0.f);
    v.y = fmaxf(fmaf(v.y, sc.y, sh.y), 0.f);
    v.z = fmaxf(fmaf(v.z, sc.z, sh.z), 0.f);
    v.w = fmaxf(fmaf(v.w, sc.w, sh.w), 0.f);
    ((float4*)g_h1)[i] = v;
}

// ---------------- layer-2 normalize + relu + decoder (fused) -----------------
__global__ void __launch_bounds__(256) final_kernel(const float* __restrict__ Wd,
                                                    const float* __restrict__ bd,
                                                    float* __restrict__ out,
                                                    int n, int C) {
    __shared__ float WdT[HDIM * 48];   // padded stride 48, zero-filled
    __shared__ float shh[8][HDIM];
    __shared__ float sbd[48];
    int tid = threadIdx.x;
    for (int i = tid; i < HDIM * 48; i += 256) WdT[i] = 0.f;
    if (tid < 48) sbd[tid] = (tid < C) ? bd[tid] : 0.f;
    __syncthreads();
    for (int i = tid; i < C * HDIM; i += 256) {
        int c = i >> 6, k = i & 63;
        WdT[k * 48 + c] = Wd[i];
    }
    __syncthreads();

    int warp = tid >> 5, lane = tid & 31;
    int j0 = 2 * lane;
    float sc0 = g_scale[j0], sc1 = g_scale[j0 + 1];
    float sh0 = g_shift[j0], sh1 = g_shift[j0 + 1];
    float* hout = out + (long long)n * C;

    for (long long node = (long long)blockIdx.x * 8 + warp; node < n;
         node += (long long)gridDim.x * 8) {
        float2 p = ((const float2*)(g_pre + node * HDIM))[lane];
        float h0 = fmaxf(fmaf(p.x, sc0, sh0), 0.f);
        float h1 = fmaxf(fmaf(p.y, sc1, sh1), 0.f);
        ((float2*)(hout + node * HDIM))[lane] = make_float2(h0, h1);
        shh[warp][j0] = h0; shh[warp][j0 + 1] = h1;
        __syncwarp();
        float a0 = 0.f, a1 = 0.f;
#pragma unroll
        for (int k = 0; k < HDIM; k++) {
            float hv = shh[warp][k];
            a0 = fmaf(hv, WdT[k * 48 + lane], a0);
            a1 = fmaf(hv, WdT[k * 48 + lane + 32], a1);
        }
        out[node * C + lane] = a0 + sbd[lane];
        if (lane + 32 < C) out[node * C + lane + 32] = a1 + sbd[lane + 32];
        __syncwarp();
    }
}

// ---------------- launch -----------------------------------------------------
extern "C" void kernel_launch(void* const* d_in, const int* in_sizes, int n_in,
                              void* d_out, int out_size) {
    const float* x   = (const float*)d_in[0];
    const void*  ei  = d_in[1];
    const float* W1l = (const float*)d_in[2];
    const float* b1l = (const float*)d_in[3];
    const float* W1r = (const float*)d_in[4];
    const float* g1  = (const float*)d_in[5];
    const float* be1 = (const float*)d_in[6];
    const float* W2l = (const float*)d_in[7];
    const float* b2l = (const float*)d_in[8];
    const float* W2r = (const float*)d_in[9];
    const float* g2  = (const float*)d_in[10];
    const float* be2 = (const float*)d_in[11];
    const float* Wd  = (const float*)d_in[12];
    const float* bd  = (const float*)d_in[13];
    float* out = (float*)d_out;

    int n = in_sizes[0] / HDIM;               // 100000
    long long E = (long long)in_sizes[1] / 2; // 1600000
    int C = in_sizes[12] / HDIM;              // 40

    float* p_h1 = nullptr;
    cudaGetSymbolAddress((void**)&p_h1, g_h1);

    long long nvec = (long long)n * 16;
    int zb = (int)((nvec + 255) / 256);
    int eb = (int)((E + 255) / 256);
    int sb = (n + 511) / 512;                 // scan blocks (196 <= 512)
    const int LAYER_GRID = 740;               // 5 blocks/SM by smem

    detect_kernel<<<1, 256>>>((const unsigned int*)ei);

    // ---- CSR build (by dst) ----
    zero_kernel<<<(n + 255) / 256, 256>>>(n);
    hist_kernel<<<eb, 256>>>(ei, E);
    scan_part<<<sb, 512>>>(n);
    scan_top<<<1, 512>>>(sb);
    scan_final<<<sb, 512>>>(n);
    fill_kernel<<<eb, 256>>>(ei, E);

    // ---- layer 1 (fused gather + linear + BN stats) ----
    layer_kernel<<<LAYER_GRID, 128>>>(x, W1l, b1l, W1r, n);
    bn_kernel<<<1, HDIM>>>(g1, be1, (float)n);
    norm_kernel<<<zb, 256>>>(nvec);

    // ---- layer 2 ----
    zero_stats<<<1, HDIM>>>();
    layer_kernel<<<LAYER_GRID, 128>>>(p_h1, W2l, b2l, W2r, n);
    bn_kernel<<<1, HDIM>>>(g2, be2, (float)n);

    // ---- normalize + relu + decoder (fused) ----
    final_kernel<<<592, 256>>>(Wd, bd, out, n, C);
}

// round 4
// speedup vs baseline: 1.6393x; 1.2237x over previous
#include <cuda_runtime.h>
#include <cuda_bf16.h>

#define NMAX 100000
#define EMAX 1600000
#define HDIM 64
#define STRIDE 96   // ELL row stride; max Poisson(16) degree over 100K nodes ~ 45

typedef unsigned long long ull;

// ---------------- scratch (device globals; no allocation allowed) -----------
__device__ __align__(256) int   g_degi[NMAX];           // degree (atomic counter)
__device__ __align__(256) int   g_ell[NMAX * STRIDE];   // neighbor ids (ELL)
__device__ __align__(256) float g_pre1[NMAX * HDIM];    // layer-1 pre-BN output
__device__ __align__(256) float g_pre2[NMAX * HDIM];    // layer-2 pre-BN output
__device__ float g_colsum[HDIM];
__device__ float g_colsq[HDIM];
__device__ float g_scale[HDIM];
__device__ float g_shift[HDIM];
__device__ int   g_is64;

// packed fp32x2 FMA (Blackwell): acc = a*b + acc, two MACs per instruction
#define FMA2(acc, a, b) \
    asm("fma.rn.f32x2 %0, %1, %2, %0;" : "+l"(acc) : "l"(a), "l"(b))

__device__ __forceinline__ float2 unpack2(ull v) {
    float2 r;
    asm("mov.b64 {%0, %1}, %2;" : "=f"(r.x), "=f"(r.y) : "l"(v));
    return r;
}

// ---------------- edge-index dtype detection --------------------------------
// jnp.int64 without jax x64 silently becomes int32. Node ids < 1e5, so under
// an int64 layout every odd 32-bit word is zero.
__global__ void detect_kernel(const unsigned int* __restrict__ ei32) {
    __shared__ unsigned int acc;
    if (threadIdx.x == 0) acc = 0u;
    __syncthreads();
    unsigned int v = 0u;
    for (int i = threadIdx.x; i < 4096; i += blockDim.x) v |= ei32[2 * i + 1];
    atomicOr(&acc, v);
    __syncthreads();
    if (threadIdx.x == 0) g_is64 = (acc == 0u) ? 1 : 0;
}

__device__ __forceinline__ long long load_idx(const void* ei, long long pos, int is64) {
    if (is64) return ((const long long*)ei)[pos];
    return (long long)((const int*)ei)[pos];
}

// ---------------- zero degree + BN stats ------------------------------------
__global__ void zero_kernel(int n) {
    int i = blockIdx.x * blockDim.x + threadIdx.x;
    if (i < n) g_degi[i] = 0;
    if (i < HDIM) { g_colsum[i] = 0.f; g_colsq[i] = 0.f; }
}

// ---------------- ELL fill (also produces degree) ---------------------------
__global__ void __launch_bounds__(256) fill_kernel(const void* __restrict__ ei,
                                                   long long E) {
    long long e = (long long)blockIdx.x * blockDim.x + threadIdx.x;
    if (e >= E) return;
    int is64 = g_is64;
    int s = (int)load_idx(ei, e, is64);
    int d = (int)load_idx(ei, E + e, is64);
    int slot = atomicAdd(&g_degi[d], 1);
    if (slot < STRIDE) g_ell[d * STRIDE + slot] = s;
}

// ---------------- fused layer ------------------------------------------------
// ELL gather-mean (+ optional on-the-fly BN+relu of the input) + stacked GEMV
// [inv*agg | root] @ [Wl; Wr]^T + bias, + BN stat accumulation.
// 256 threads (8 warps); each warp processes 4 nodes per iteration.
// Input (xin) and output (yout) MUST be distinct buffers (no aliasing: the
// gather reads arbitrary rows of xin while yout rows are being written).
__global__ void __launch_bounds__(256) layer_kernel(
    const float* __restrict__ xin, float* __restrict__ yout,
    const float* __restrict__ Wl, const float* __restrict__ bl,
    const float* __restrict__ Wr, int apply_norm, int n)
{
    __shared__ __align__(16) ull   sW[2][64][32];        // 32 KB
    __shared__ __align__(16) float shV[8][4][2 * HDIM];  // 16 KB

    int tid = threadIdx.x;
    for (int i = tid; i < 4096; i += 256) {
        int m = i >> 11, kp = (i >> 5) & 63, ln = i & 31;
        int row = 2 * ln + m;
        ull w = (kp < 32) ? ((const ull*)Wl)[row * 32 + kp]
                          : ((const ull*)Wr)[row * 32 + (kp - 32)];
        sW[m][kp][ln] = w;
    }
    __syncthreads();

    int warp = tid >> 5, lane = tid & 31;
    int j0 = 2 * lane;
    float b0 = bl[j0], b1 = bl[j0 + 1];
    float sc0 = 1.f, sc1 = 1.f, sh0 = 0.f, sh1 = 0.f;
    if (apply_norm) {
        sc0 = g_scale[j0]; sc1 = g_scale[j0 + 1];
        sh0 = g_shift[j0]; sh1 = g_shift[j0 + 1];
    }
    float s0 = 0.f, s1 = 0.f, q0 = 0.f, q1 = 0.f;

    for (long long grp = (long long)blockIdx.x * 8 + warp; grp * 4 < n;
         grp += (long long)gridDim.x * 8) {
        long long node0 = grp * 4;
        int nvalid = (n - node0 >= 4) ? 4 : (int)(n - node0);

        // ---- gather (+optional norm) into smem staging ----
        for (int nd = 0; nd < nvalid; nd++) {
            long long node = node0 + nd;
            int deg = g_degi[node];
            int dcap = min(deg, STRIDE);
            const int* nb = g_ell + node * STRIDE;
            float ax = 0.f, ay = 0.f;
            for (int base = 0; base < dcap; base += 32) {
                int cnt = min(32, dcap - base);
                int myid = nb[base + lane];   // in-bounds even past cnt
                int j = 0;
                for (; j + 4 <= cnt; j += 4) {
                    int i0 = __shfl_sync(0xffffffffu, myid, j);
                    int i1 = __shfl_sync(0xffffffffu, myid, j + 1);
                    int i2 = __shfl_sync(0xffffffffu, myid, j + 2);
                    int i3 = __shfl_sync(0xffffffffu, myid, j + 3);
                    float2 v0 = __ldg((const float2*)(xin + (long long)i0 * HDIM) + lane);
                    float2 v1 = __ldg((const float2*)(xin + (long long)i1 * HDIM) + lane);
                    float2 v2 = __ldg((const float2*)(xin + (long long)i2 * HDIM) + lane);
                    float2 v3 = __ldg((const float2*)(xin + (long long)i3 * HDIM) + lane);
                    if (apply_norm) {
                        v0.x = fmaxf(fmaf(v0.x, sc0, sh0), 0.f);
                        v0.y = fmaxf(fmaf(v0.y, sc1, sh1), 0.f);
                        v1.x = fmaxf(fmaf(v1.x, sc0, sh0), 0.f);
                        v1.y = fmaxf(fmaf(v1.y, sc1, sh1), 0.f);
                        v2.x = fmaxf(fmaf(v2.x, sc0, sh0), 0.f);
                        v2.y = fmaxf(fmaf(v2.y, sc1, sh1), 0.f);
                        v3.x = fmaxf(fmaf(v3.x, sc0, sh0), 0.f);
                        v3.y = fmaxf(fmaf(v3.y, sc1, sh1), 0.f);
                    }
                    ax += (v0.x + v1.x) + (v2.x + v3.x);
                    ay += (v0.y + v1.y) + (v2.y + v3.y);
                }
                for (; j < cnt; j++) {
                    int ii = __shfl_sync(0xffffffffu, myid, j);
                    float2 v = __ldg((const float2*)(xin + (long long)ii * HDIM) + lane);
                    if (apply_norm) {
                        v.x = fmaxf(fmaf(v.x, sc0, sh0), 0.f);
                        v.y = fmaxf(fmaf(v.y, sc1, sh1), 0.f);
                    }
                    ax += v.x; ay += v.y;
                }
            }
            float inv = 1.0f / fmaxf((float)deg, 1.0f);
            ax *= inv; ay *= inv;
            float2 xv = __ldg((const float2*)(xin + node * HDIM) + lane);
            if (apply_norm) {
                xv.x = fmaxf(fmaf(xv.x, sc0, sh0), 0.f);
                xv.y = fmaxf(fmaf(xv.y, sc1, sh1), 0.f);
            }
            shV[warp][nd][j0] = ax;
            shV[warp][nd][j0 + 1] = ay;
            shV[warp][nd][HDIM + j0] = xv.x;
            shV[warp][nd][HDIM + j0 + 1] = xv.y;
        }
        __syncwarp();

        // ---- stacked GEMV: K=128, packed f32x2, 4 nodes share weight reads ----
        ull aO0[4] = {0, 0, 0, 0}, aO1[4] = {0, 0, 0, 0};
#pragma unroll 8
        for (int kp = 0; kp < 64; kp++) {
            ull w0 = sW[0][kp][lane];
            ull w1 = sW[1][kp][lane];
#pragma unroll
            for (int nd = 0; nd < 4; nd++) {
                ull v = *(const ull*)&shV[warp][nd][2 * kp];
                FMA2(aO0[nd], v, w0);
                FMA2(aO1[nd], v, w1);
            }
        }
#pragma unroll
        for (int nd = 0; nd < 4; nd++) {
            if (nd < nvalid) {
                float2 o0p = unpack2(aO0[nd]);
                float2 o1p = unpack2(aO1[nd]);
                float o0 = o0p.x + o0p.y + b0;
                float o1 = o1p.x + o1p.y + b1;
                long long node = node0 + nd;
                ((float2*)(yout + node * HDIM))[lane] = make_float2(o0, o1);
                s0 += o0; s1 += o1; q0 += o0 * o0; q1 += o1 * o1;
            }
        }
        __syncwarp();
    }
    atomicAdd(&g_colsum[j0],     s0);
    atomicAdd(&g_colsum[j0 + 1], s1);
    atomicAdd(&g_colsq[j0],      q0);
    atomicAdd(&g_colsq[j0 + 1],  q1);
}

// ---------------- BN stats -> scale/shift (and reset stats) ------------------
__global__ void bn_kernel(const float* __restrict__ gamma,
                          const float* __restrict__ beta, float fn) {
    int j = threadIdx.x;
    float mean = g_colsum[j] / fn;
    float var = g_colsq[j] / fn - mean * mean;
    float sc = gamma[j] * rsqrtf(var + 1e-5f);
    g_scale[j] = sc;
    g_shift[j] = beta[j] - mean * sc;
    g_colsum[j] = 0.f;   // ready for next layer's accumulation
    g_colsq[j]  = 0.f;
}

// ---------------- layer-2 normalize + relu + decoder (fused) -----------------
// Reads g_pre2; writes logits to d_out[0 .. N*C) and h to d_out[N*C ..].
__global__ void __launch_bounds__(256) final_kernel(const float* __restrict__ Wd,
                                                    const float* __restrict__ bd,
                                                    float* __restrict__ out,
                                                    int n, int C) {
    __shared__ float WdT[HDIM * 48];   // padded stride 48, zero-filled
    __shared__ float shh[8][HDIM];
    __shared__ float sbd[48];
    int tid = threadIdx.x;
    for (int i = tid; i < HDIM * 48; i += 256) WdT[i] = 0.f;
    if (tid < 48) sbd[tid] = (tid < C) ? bd[tid] : 0.f;
    __syncthreads();
    for (int i = tid; i < C * HDIM; i += 256) {
        int c = i >> 6, k = i & 63;
        WdT[k * 48 + c] = Wd[i];
    }
    __syncthreads();

    int warp = tid >> 5, lane = tid & 31;
    int j0 = 2 * lane;
    float sc0 = g_scale[j0], sc1 = g_scale[j0 + 1];
    float sh0 = g_shift[j0], sh1 = g_shift[j0 + 1];
    float* hout = out + (long long)n * C;

    for (long long node = (long long)blockIdx.x * 8 + warp; node < n;
         node += (long long)gridDim.x * 8) {
        float2 p = ((const float2*)(g_pre2 + node * HDIM))[lane];
        float h0 = fmaxf(fmaf(p.x, sc0, sh0), 0.f);
        float h1 = fmaxf(fmaf(p.y, sc1, sh1), 0.f);
        ((float2*)(hout + node * HDIM))[lane] = make_float2(h0, h1);
        shh[warp][j0] = h0; shh[warp][j0 + 1] = h1;
        __syncwarp();
        float a0 = 0.f, a1 = 0.f;
#pragma unroll
        for (int k = 0; k < HDIM; k++) {
            float hv = shh[warp][k];
            a0 = fmaf(hv, WdT[k * 48 + lane], a0);
            a1 = fmaf(hv, WdT[k * 48 + lane + 32], a1);
        }
        out[node * C + lane] = a0 + sbd[lane];
        if (lane + 32 < C) out[node * C + lane + 32] = a1 + sbd[lane + 32];
        __syncwarp();
    }
}

// ---------------- launch -----------------------------------------------------
extern "C" void kernel_launch(void* const* d_in, const int* in_sizes, int n_in,
                              void* d_out, int out_size) {
    const float* x   = (const float*)d_in[0];
    const void*  ei  = d_in[1];
    const float* W1l = (const float*)d_in[2];
    const float* b1l = (const float*)d_in[3];
    const float* W1r = (const float*)d_in[4];
    const float* g1  = (const float*)d_in[5];
    const float* be1 = (const float*)d_in[6];
    const float* W2l = (const float*)d_in[7];
    const float* b2l = (const float*)d_in[8];
    const float* W2r = (const float*)d_in[9];
    const float* g2  = (const float*)d_in[10];
    const float* be2 = (const float*)d_in[11];
    const float* Wd  = (const float*)d_in[12];
    const float* bd  = (const float*)d_in[13];
    float* out = (float*)d_out;

    int n = in_sizes[0] / HDIM;               // 100000
    long long E = (long long)in_sizes[1] / 2; // 1600000
    int C = in_sizes[12] / HDIM;              // 40

    float* p_pre1 = nullptr;
    float* p_pre2 = nullptr;
    cudaGetSymbolAddress((void**)&p_pre1, g_pre1);
    cudaGetSymbolAddress((void**)&p_pre2, g_pre2);

    int eb = (int)((E + 255) / 256);
    const int LAYER_GRID = 592;   // 4 blocks/SM

    // launch order matters for profiling: layer_kernel (L1) is the 4th launch
    detect_kernel<<<1, 256>>>((const unsigned int*)ei);                    // 1
    zero_kernel<<<(n + 255) / 256, 256>>>(n);                              // 2
    fill_kernel<<<eb, 256>>>(ei, E);                                       // 3

    layer_kernel<<<LAYER_GRID, 256>>>(x, p_pre1, W1l, b1l, W1r, 0, n);     // 4 (profiled)
    bn_kernel<<<1, HDIM>>>(g1, be1, (float)n);                             // 5

    layer_kernel<<<LAYER_GRID, 256>>>(p_pre1, p_pre2, W2l, b2l, W2r, 1, n);// 6
    bn_kernel<<<1, HDIM>>>(g2, be2, (float)n);                             // 7

    final_kernel<<<LAYER_GRID, 256>>>(Wd, bd, out, n, C);                  // 8
}

// round 5
// speedup vs baseline: 1.6409x; 1.0009x over previous
#include <cuda_runtime.h>
#include <cuda_bf16.h>

#define NMAX 100000
#define EMAX 1600000
#define HDIM 64
#define STRIDE 96   // ELL row stride; max Poisson(16) degree over 100K nodes ~ 45

typedef unsigned long long ull;

// ---------------- scratch (device globals; no allocation allowed) -----------
__device__ __align__(256) int   g_degi[NMAX];           // degree (atomic counter)
__device__ __align__(256) int   g_ell[NMAX * STRIDE];   // neighbor ids (ELL)
__device__ __align__(256) float g_pre1[NMAX * HDIM];    // layer-1 pre-BN output
__device__ __align__(256) float g_pre2[NMAX * HDIM];    // layer-2 pre-BN output
__device__ float g_colsum[HDIM];
__device__ float g_colsq[HDIM];
__device__ float g_scale[HDIM];
__device__ float g_shift[HDIM];
__device__ int   g_is64;

// packed fp32x2 FMA (Blackwell): acc = a*b + acc, two MACs per instruction
#define FMA2(acc, a, b) \
    asm("fma.rn.f32x2 %0, %1, %2, %0;" : "+l"(acc) : "l"(a), "l"(b))

__device__ __forceinline__ float2 unpack2(ull v) {
    float2 r;
    asm("mov.b64 {%0, %1}, %2;" : "=f"(r.x), "=f"(r.y) : "l"(v));
    return r;
}

// ---------------- edge-index dtype detection --------------------------------
// jnp.int64 without jax x64 silently becomes int32. Node ids < 1e5, so under
// an int64 layout every odd 32-bit word is zero.
__global__ void detect_kernel(const unsigned int* __restrict__ ei32) {
    __shared__ unsigned int acc;
    if (threadIdx.x == 0) acc = 0u;
    __syncthreads();
    unsigned int v = 0u;
    for (int i = threadIdx.x; i < 4096; i += blockDim.x) v |= ei32[2 * i + 1];
    atomicOr(&acc, v);
    __syncthreads();
    if (threadIdx.x == 0) g_is64 = (acc == 0u) ? 1 : 0;
}

__device__ __forceinline__ long long load_idx(const void* ei, long long pos, int is64) {
    if (is64) return ((const long long*)ei)[pos];
    return (long long)((const int*)ei)[pos];
}

// ---------------- zero degree + BN stats ------------------------------------
__global__ void zero_kernel(int n) {
    int i = blockIdx.x * blockDim.x + threadIdx.x;
    if (i < n) g_degi[i] = 0;
    if (i < HDIM) { g_colsum[i] = 0.f; g_colsq[i] = 0.f; }
}

// ---------------- ELL fill (also produces degree) ---------------------------
__global__ void __launch_bounds__(256) fill_kernel(const void* __restrict__ ei,
                                                   long long E) {
    long long e = (long long)blockIdx.x * blockDim.x + threadIdx.x;
    if (e >= E) return;
    int is64 = g_is64;
    int s = (int)load_idx(ei, e, is64);
    int d = (int)load_idx(ei, E + e, is64);
    int slot = atomicAdd(&g_degi[d], 1);
    if (slot < STRIDE) g_ell[d * STRIDE + slot] = s;
}

// ---------------- fused layer ------------------------------------------------
// ELL gather-mean (+ optional on-the-fly BN+relu of the input) + stacked GEMV
// [inv*agg | root] @ [Wl; Wr]^T + bias, + BN stat accumulation.
// 256 threads (8 warps); each warp processes 4 nodes per iteration.
// Input (xin) and output (yout) MUST be distinct buffers (no aliasing: the
// gather reads arbitrary rows of xin while yout rows are being written).
__global__ void __launch_bounds__(256) layer_kernel(
    const float* __restrict__ xin, float* __restrict__ yout,
    const float* __restrict__ Wl, const float* __restrict__ bl,
    const float* __restrict__ Wr, int apply_norm, int n)
{
    __shared__ __align__(16) ull   sW[2][64][32];        // 32 KB
    __shared__ __align__(16) float shV[8][4][2 * HDIM];  // 16 KB

    int tid = threadIdx.x;
    for (int i = tid; i < 4096; i += 256) {
        int m = i >> 11, kp = (i >> 5) & 63, ln = i & 31;
        int row = 2 * ln + m;
        ull w = (kp < 32) ? ((const ull*)Wl)[row * 32 + kp]
                          : ((const ull*)Wr)[row * 32 + (kp - 32)];
        sW[m][kp][ln] = w;
    }
    __syncthreads();

    int warp = tid >> 5, lane = tid & 31;
    int j0 = 2 * lane;
    float b0 = bl[j0], b1 = bl[j0 + 1];
    float sc0 = 1.f, sc1 = 1.f, sh0 = 0.f, sh1 = 0.f;
    if (apply_norm) {
        sc0 = g_scale[j0]; sc1 = g_scale[j0 + 1];
        sh0 = g_shift[j0]; sh1 = g_shift[j0 + 1];
    }
    float s0 = 0.f, s1 = 0.f, q0 = 0.f, q1 = 0.f;

    for (long long grp = (long long)blockIdx.x * 8 + warp; grp * 4 < n;
         grp += (long long)gridDim.x * 8) {
        long long node0 = grp * 4;
        int nvalid = (n - node0 >= 4) ? 4 : (int)(n - node0);

        // ---- gather (+optional norm) into smem staging ----
        for (int nd = 0; nd < nvalid; nd++) {
            long long node = node0 + nd;
            int deg = g_degi[node];
            int dcap = min(deg, STRIDE);
            const int* nb = g_ell + node * STRIDE;
            float ax = 0.f, ay = 0.f;
            for (int base = 0; base < dcap; base += 32) {
                int cnt = min(32, dcap - base);
                int myid = nb[base + lane];   // in-bounds even past cnt
                int j = 0;
                for (; j + 4 <= cnt; j += 4) {
                    int i0 = __shfl_sync(0xffffffffu, myid, j);
                    int i1 = __shfl_sync(0xffffffffu, myid, j + 1);
                    int i2 = __shfl_sync(0xffffffffu, myid, j + 2);
                    int i3 = __shfl_sync(0xffffffffu, myid, j + 3);
                    float2 v0 = __ldg((const float2*)(xin + (long long)i0 * HDIM) + lane);
                    float2 v1 = __ldg((const float2*)(xin + (long long)i1 * HDIM) + lane);
                    float2 v2 = __ldg((const float2*)(xin + (long long)i2 * HDIM) + lane);
                    float2 v3 = __ldg((const float2*)(xin + (long long)i3 * HDIM) + lane);
                    if (apply_norm) {
                        v0.x = fmaxf(fmaf(v0.x, sc0, sh0), 0.f);
                        v0.y = fmaxf(fmaf(v0.y, sc1, sh1), 0.f);
                        v1.x = fmaxf(fmaf(v1.x, sc0, sh0), 0.f);
                        v1.y = fmaxf(fmaf(v1.y, sc1, sh1), 0.f);
                        v2.x = fmaxf(fmaf(v2.x, sc0, sh0), 0.f);
                        v2.y = fmaxf(fmaf(v2.y, sc1, sh1), 0.f);
                        v3.x = fmaxf(fmaf(v3.x, sc0, sh0), 0.f);
                        v3.y = fmaxf(fmaf(v3.y, sc1, sh1), 0.f);
                    }
                    ax += (v0.x + v1.x) + (v2.x + v3.x);
                    ay += (v0.y + v1.y) + (v2.y + v3.y);
                }
                for (; j < cnt; j++) {
                    int ii = __shfl_sync(0xffffffffu, myid, j);
                    float2 v = __ldg((const float2*)(xin + (long long)ii * HDIM) + lane);
                    if (apply_norm) {
                        v.x = fmaxf(fmaf(v.x, sc0, sh0), 0.f);
                        v.y = fmaxf(fmaf(v.y, sc1, sh1), 0.f);
                    }
                    ax += v.x; ay += v.y;
                }
            }
            float inv = 1.0f / fmaxf((float)deg, 1.0f);
            ax *= inv; ay *= inv;
            float2 xv = __ldg((const float2*)(xin + node * HDIM) + lane);
            if (apply_norm) {
                xv.x = fmaxf(fmaf(xv.x, sc0, sh0), 0.f);
                xv.y = fmaxf(fmaf(xv.y, sc1, sh1), 0.f);
            }
            shV[warp][nd][j0] = ax;
            shV[warp][nd][j0 + 1] = ay;
            shV[warp][nd][HDIM + j0] = xv.x;
            shV[warp][nd][HDIM + j0 + 1] = xv.y;
        }
        __syncwarp();

        // ---- stacked GEMV: K=128, packed f32x2, 4 nodes share weight reads ----
        ull aO0[4] = {0, 0, 0, 0}, aO1[4] = {0, 0, 0, 0};
#pragma unroll 8
        for (int kp = 0; kp < 64; kp++) {
            ull w0 = sW[0][kp][lane];
            ull w1 = sW[1][kp][lane];
#pragma unroll
            for (int nd = 0; nd < 4; nd++) {
                ull v = *(const ull*)&shV[warp][nd][2 * kp];
                FMA2(aO0[nd], v, w0);
                FMA2(aO1[nd], v, w1);
            }
        }
#pragma unroll
        for (int nd = 0; nd < 4; nd++) {
            if (nd < nvalid) {
                float2 o0p = unpack2(aO0[nd]);
                float2 o1p = unpack2(aO1[nd]);
                float o0 = o0p.x + o0p.y + b0;
                float o1 = o1p.x + o1p.y + b1;
                long long node = node0 + nd;
                ((float2*)(yout + node * HDIM))[lane] = make_float2(o0, o1);
                s0 += o0; s1 += o1; q0 += o0 * o0; q1 += o1 * o1;
            }
        }
        __syncwarp();
    }
    atomicAdd(&g_colsum[j0],     s0);
    atomicAdd(&g_colsum[j0 + 1], s1);
    atomicAdd(&g_colsq[j0],      q0);
    atomicAdd(&g_colsq[j0 + 1],  q1);
}

// ---------------- BN stats -> scale/shift (and reset stats) ------------------
__global__ void bn_kernel(const float* __restrict__ gamma,
                          const float* __restrict__ beta, float fn) {
    int j = threadIdx.x;
    float mean = g_colsum[j] / fn;
    float var = g_colsq[j] / fn - mean * mean;
    float sc = gamma[j] * rsqrtf(var + 1e-5f);
    g_scale[j] = sc;
    g_shift[j] = beta[j] - mean * sc;
    g_colsum[j] = 0.f;   // ready for next layer's accumulation
    g_colsq[j]  = 0.f;
}

// ---------------- layer-2 normalize + relu + decoder (fused) -----------------
// Reads g_pre2; writes logits to d_out[0 .. N*C) and h to d_out[N*C ..].
__global__ void __launch_bounds__(256) final_kernel(const float* __restrict__ Wd,
                                                    const float* __restrict__ bd,
                                                    float* __restrict__ out,
                                                    int n, int C) {
    __shared__ float WdT[HDIM * 48];   // padded stride 48, zero-filled
    __shared__ float shh[8][HDIM];
    __shared__ float sbd[48];
    int tid = threadIdx.x;
    for (int i = tid; i < HDIM * 48; i += 256) WdT[i] = 0.f;
    if (tid < 48) sbd[tid] = (tid < C) ? bd[tid] : 0.f;
    __syncthreads();
    for (int i = tid; i < C * HDIM; i += 256) {
        int c = i >> 6, k = i & 63;
        WdT[k * 48 + c] = Wd[i];
    }
    __syncthreads();

    int warp = tid >> 5, lane = tid & 31;
    int j0 = 2 * lane;
    float sc0 = g_scale[j0], sc1 = g_scale[j0 + 1];
    float sh0 = g_shift[j0], sh1 = g_shift[j0 + 1];
    float* hout = out + (long long)n * C;

    for (long long node = (long long)blockIdx.x * 8 + warp; node < n;
         node += (long long)gridDim.x * 8) {
        float2 p = ((const float2*)(g_pre2 + node * HDIM))[lane];
        float h0 = fmaxf(fmaf(p.x, sc0, sh0), 0.f);
        float h1 = fmaxf(fmaf(p.y, sc1, sh1), 0.f);
        ((float2*)(hout + node * HDIM))[lane] = make_float2(h0, h1);
        shh[warp][j0] = h0; shh[warp][j0 + 1] = h1;
        __syncwarp();
        float a0 = 0.f, a1 = 0.f;
#pragma unroll
        for (int k = 0; k < HDIM; k++) {
            float hv = shh[warp][k];
            a0 = fmaf(hv, WdT[k * 48 + lane], a0);
            a1 = fmaf(hv, WdT[k * 48 + lane + 32], a1);
        }
        out[node * C + lane] = a0 + sbd[lane];
        if (lane + 32 < C) out[node * C + lane + 32] = a1 + sbd[lane + 32];
        __syncwarp();
    }
}

// ---------------- launch -----------------------------------------------------
extern "C" void kernel_launch(void* const* d_in, const int* in_sizes, int n_in,
                              void* d_out, int out_size) {
    const float* x   = (const float*)d_in[0];
    const void*  ei  = d_in[1];
    const float* W1l = (const float*)d_in[2];
    const float* b1l = (const float*)d_in[3];
    const float* W1r = (const float*)d_in[4];
    const float* g1  = (const float*)d_in[5];
    const float* be1 = (const float*)d_in[6];
    const float* W2l = (const float*)d_in[7];
    const float* b2l = (const float*)d_in[8];
    const float* W2r = (const float*)d_in[9];
    const float* g2  = (const float*)d_in[10];
    const float* be2 = (const float*)d_in[11];
    const float* Wd  = (const float*)d_in[12];
    const float* bd  = (const float*)d_in[13];
    float* out = (float*)d_out;

    int n = in_sizes[0] / HDIM;               // 100000
    long long E = (long long)in_sizes[1] / 2; // 1600000
    int C = in_sizes[12] / HDIM;              // 40

    float* p_pre1 = nullptr;
    float* p_pre2 = nullptr;
    cudaGetSymbolAddress((void**)&p_pre1, g_pre1);
    cudaGetSymbolAddress((void**)&p_pre2, g_pre2);

    int eb = (int)((E + 255) / 256);
    const int LAYER_GRID = 592;   // 4 blocks/SM

    // launch order matters for profiling: layer_kernel (L1) is the 4th launch
    detect_kernel<<<1, 256>>>((const unsigned int*)ei);                    // 1
    zero_kernel<<<(n + 255) / 256, 256>>>(n);                              // 2
    fill_kernel<<<eb, 256>>>(ei, E);                                       // 3

    layer_kernel<<<LAYER_GRID, 256>>>(x, p_pre1, W1l, b1l, W1r, 0, n);     // 4 (profiled)
    bn_kernel<<<1, HDIM>>>(g1, be1, (float)n);                             // 5

    layer_kernel<<<LAYER_GRID, 256>>>(p_pre1, p_pre2, W2l, b2l, W2r, 1, n);// 6
    bn_kernel<<<1, HDIM>>>(g2, be2, (float)n);                             // 7

    final_kernel<<<LAYER_GRID, 256>>>(Wd, bd, out, n, C);                  // 8
}